// round 10
// baseline (speedup 1.0000x reference)
#include <cuda_runtime.h>
#include <cstdint>
#include <cstddef>

// Problem constants
#define NEXP 8
#define TOPK 2
#define DIM 1024
#define DFF 4096
#define NTOK 16384          // B*S
#define CAP  16384          // per-expert capacity
#define RTOT (NTOK * TOPK)  // 32768 expert-rows
#define PADR 128            // row padding for tile overrun

// ---------------- scratch (device globals; DEVICE-CODE REFERENCES ONLY) ------
// RULE (rounds 2-5): never pass these symbols as host-side kernel args — the
// host shadow is ATS-readable on GB300 and silently reads zeros.
__device__ int   g_cnt[NEXP];
__device__ int   g_off[NEXP];
__device__ int   g_tok[NEXP * CAP];
__device__ int   g_dst[NEXP * CAP];
__device__ float g_wtl[NEXP * CAP];
__device__ float g_Xg[(size_t)(RTOT + PADR) * DIM];   // gathered + tf32-rounded x
__device__ float g_H [(size_t)(RTOT + PADR) * DFF];   // hidden scratch (tf32)
__device__ float g_O [(size_t)RTOT * DIM];            // per-slot outputs
__device__ float g_W1t[(size_t)NEXP * DIM * DFF];     // W1^T: [DFF][DIM], tf32
__device__ float g_W2t[(size_t)NEXP * DFF * DIM];     // W2^T: [DIM][DFF], tf32

// ---------------- helpers ----------------------------------------------------
__device__ __forceinline__ float tf32r(float f) {
    unsigned u;
    asm volatile("cvt.rna.tf32.f32 %0, %1;" : "=r"(u) : "f"(f));
    return __uint_as_float(u);
}
__device__ __forceinline__ void mma_tf32(float c[4], const unsigned a[4], const unsigned b[2]) {
    asm volatile(
        "mma.sync.aligned.m16n8k8.row.col.f32.tf32.tf32.f32 "
        "{%0,%1,%2,%3}, {%4,%5,%6,%7}, {%8,%9}, {%0,%1,%2,%3};\n"
        : "+f"(c[0]), "+f"(c[1]), "+f"(c[2]), "+f"(c[3])
        : "r"(a[0]), "r"(a[1]), "r"(a[2]), "r"(a[3]), "r"(b[0]), "r"(b[1]));
}
__device__ __forceinline__ void ldsm_x4(unsigned& r0, unsigned& r1, unsigned& r2,
                                        unsigned& r3, uint32_t addr) {
    asm volatile("ldmatrix.sync.aligned.m8n8.x4.shared.b16 {%0,%1,%2,%3}, [%4];"
                 : "=r"(r0), "=r"(r1), "=r"(r2), "=r"(r3) : "r"(addr));
}
__device__ __forceinline__ void cpasync16(uint32_t d, const void* s) {
    asm volatile("cp.async.cg.shared.global [%0], [%1], 16;" :: "r"(d), "l"(s));
}
__device__ __forceinline__ void cp_commit() { asm volatile("cp.async.commit_group;"); }
template <int N>
__device__ __forceinline__ void cp_wait() {
    asm volatile("cp.async.wait_group %0;" :: "n"(N));
}

// ---------------- kernel 0-2: routing ----------------------------------------
__global__ void zero_kernel() {
    if (threadIdx.x < NEXP) g_cnt[threadIdx.x] = 0;
}

__global__ void route_kernel(const float* __restrict__ x, const float* __restrict__ gw) {
    __shared__ float s_gw[NEXP * DIM];
    int tid = threadIdx.x;
    for (int i = tid; i < NEXP * DIM; i += blockDim.x) s_gw[i] = gw[i];
    __syncthreads();

    int warp = tid >> 5, lane = tid & 31;
    int t = blockIdx.x * (blockDim.x >> 5) + warp;
    if (t >= NTOK) return;

    const float* xr = x + (size_t)t * DIM;
    float xv[32];
#pragma unroll
    for (int i = 0; i < 32; i++) xv[i] = xr[i * 32 + lane];

    float logit[NEXP];
#pragma unroll
    for (int e = 0; e < NEXP; e++) {
        float acc = 0.f;
#pragma unroll
        for (int i = 0; i < 32; i++) acc += xv[i] * s_gw[e * DIM + i * 32 + lane];
#pragma unroll
        for (int o = 16; o; o >>= 1) acc += __shfl_xor_sync(0xffffffffu, acc, o);
        logit[e] = acc;
    }

    if (lane == 0) {
        int i0 = 0;
#pragma unroll
        for (int e = 1; e < NEXP; e++) if (logit[e] > logit[i0]) i0 = e;
        int i1 = (i0 == 0) ? 1 : 0;
#pragma unroll
        for (int e = 0; e < NEXP; e++) {
            if (e == i0 || e == i1) continue;
            if (logit[e] > logit[i1]) i1 = e;
        }
        float ee = __expf(logit[i1] - logit[i0]);
        float inv = 1.f / (1.f + ee);
        int p0 = atomicAdd(&g_cnt[i0], 1);
        g_tok[i0 * CAP + p0] = t;  g_dst[i0 * CAP + p0] = t * 2;      g_wtl[i0 * CAP + p0] = inv;
        int p1 = atomicAdd(&g_cnt[i1], 1);
        g_tok[i1 * CAP + p1] = t;  g_dst[i1 * CAP + p1] = t * 2 + 1;  g_wtl[i1 * CAP + p1] = ee * inv;
    }
}

__global__ void prefix_kernel() {
    if (threadIdx.x == 0) {
        int s = 0;
#pragma unroll
        for (int e = 0; e < NEXP; e++) { g_off[e] = s; s += g_cnt[e]; }
    }
}

// ---------------- kernel 3: weight prep: tf32 round + transpose to [N][K] -----
template <int WHICH>   // 0: W1 (K=DIM, N=DFF) -> g_W1t;  1: W2 (K=DFF, N=DIM) -> g_W2t
__global__ void wprep_kernel(const float* __restrict__ src) {
    constexpr int K = WHICH ? DFF : DIM;
    constexpr int N = WHICH ? DIM : DFF;
    __shared__ float t[32][33];
    float* dall = WHICH ? g_W2t : g_W1t;           // device-side symbol
    int e = blockIdx.z;
    const float* s = src + (size_t)e * K * N;
    float* d = dall + (size_t)e * K * N;
    int nb = blockIdx.x * 32, kb = blockIdx.y * 32;
    int tx = threadIdx.x, ty = threadIdx.y;        // block (32, 8)
#pragma unroll
    for (int j = 0; j < 4; j++)
        t[ty + j * 8][tx] = s[(size_t)(kb + ty + j * 8) * N + nb + tx];
    __syncthreads();
#pragma unroll
    for (int j = 0; j < 4; j++)
        d[(size_t)(nb + ty + j * 8) * K + kb + tx] = tf32r(t[tx][ty + j * 8]);
}

// ---------------- kernel 4: gather + round x ----------------------------------
__global__ void gather_kernel(const float* __restrict__ x) {
    int e = blockIdx.y, m = blockIdx.x;
    if (m >= g_cnt[e]) return;
    int tok = g_tok[e * CAP + m];
    int row = g_off[e] + m;
    const float4* src = (const float4*)(x + (size_t)tok * DIM);
    float4* dst = (float4*)(g_Xg + (size_t)row * DIM);
    float4 v = src[threadIdx.x];
    v.x = tf32r(v.x); v.y = tf32r(v.y); v.z = tf32r(v.z); v.w = tf32r(v.w);
    dst[threadIdx.x] = v;
}

// ---------------- kernels 5/6: cp.async + ldmatrix grouped GEMM ---------------
// Both A and B tiles are K-major rows with +4 padding (row stride 36 floats),
// so every mma fragment loads via ldmatrix.x4 (conflict-free: 9r mod 8 spans
// all banks).  B comes from pre-transposed W^T [N][K].
// MODE 0: H = silu(Xg @ W1 + b1)    (KDIM=DIM,  NDIM=DFF)
// MODE 1: O = (H @ W2 + b2) * wt    (KDIM=DFF,  NDIM=DIM)
template <int KDIM, int NDIM, int MODE>
__global__ void __launch_bounds__(256, 1) ffn_gemm(const float* __restrict__ ball) {
    constexpr int BM = 128, BN = 256, BK = 32, STAGES = 3;
    constexpr int RS = BK + 4;                  // row stride (floats)
    constexpr int SA = BM * RS;                 // 4608 floats
    constexpr int SB = BN * RS;                 // 9216 floats
    constexpr int SS = SA + SB;                 // 13824 floats / stage
    constexpr int KT = KDIM / BK;
    constexpr int NN = NDIM / BN;
    constexpr int GM = 16;                      // raster group (L2 reuse)

    extern __shared__ float sm[];

    const float* Ain = (MODE == 0) ? g_Xg : g_H;      // device symbols
    const float* Wt  = (MODE == 0) ? g_W1t : g_W2t;

    int e = blockIdx.z;
    int cnt = g_cnt[e];
    int per = GM * NN;
    int grp = blockIdx.x / per;
    int rem = blockIdx.x - grp * per;
    int mb = grp * GM + (rem % GM);
    int nb = rem / GM;
    int m0 = mb * BM;
    if (m0 >= cnt) return;
    int n0 = nb * BN;
    int off = g_off[e];

    const float* Abase = Ain + (size_t)(off + m0) * KDIM;
    const float* Bbase = Wt + (size_t)e * KDIM * NDIM + (size_t)n0 * KDIM;
    const float* bias = ball + (size_t)e * NDIM;

    int tid = threadIdx.x;
    int warp = tid >> 5, lane = tid & 31;
    int wm = warp & 1, wn = warp >> 1;           // 2 (M) x 4 (N); warp tile 64x64
    int group = lane >> 2, tig = lane & 3;

    uint32_t sbase = (uint32_t)__cvta_generic_to_shared(sm);

    // staging maps (16B chunks): A 1024 chunks, B 2048 chunks, 12/thread
    const float* a_src[4];
    uint32_t a_dst[4];
#pragma unroll
    for (int i = 0; i < 4; i++) {
        int c = tid + 256 * i;                   // 128 rows x 8 chunks
        int r = c >> 3, s = c & 7;
        a_src[i] = Abase + (size_t)r * KDIM + s * 4;
        a_dst[i] = (uint32_t)((r * RS + s * 4) * 4);
    }
    const float* b_src[8];
    uint32_t b_dst[8];
#pragma unroll
    for (int i = 0; i < 8; i++) {
        int c = tid + 256 * i;                   // 256 rows x 8 chunks
        int n = c >> 3, s = c & 7;
        b_src[i] = Bbase + (size_t)n * KDIM + s * 4;
        b_dst[i] = (uint32_t)((SA + n * RS + s * 4) * 4);
    }

    auto issue = [&](int kt, int stage) {
        uint32_t sb = sbase + (uint32_t)(stage * SS * 4);
#pragma unroll
        for (int i = 0; i < 4; i++)
            cpasync16(sb + a_dst[i], a_src[i] + (size_t)kt * BK);
#pragma unroll
        for (int i = 0; i < 8; i++)
            cpasync16(sb + b_dst[i], b_src[i] + (size_t)kt * BK);
    };

    // ldmatrix per-thread address components
    int arow = lane & 15;                        // A: row within 16-block
    int acoff = (lane >> 4) * 4;                 // A: k offset 0 / 4
    int brow = (lane & 7) + ((lane >> 4) << 3);  // B: n row within 16-block
    int bcoff = ((lane >> 3) & 1) * 4;           // B: k offset 0 / 4

    float acc[4][8][4];
#pragma unroll
    for (int mi = 0; mi < 4; mi++)
#pragma unroll
        for (int ni = 0; ni < 8; ni++)
#pragma unroll
            for (int r = 0; r < 4; r++) acc[mi][ni][r] = 0.f;

    issue(0, 0); cp_commit();
    issue(1, 1); cp_commit();

    for (int kt = 0; kt < KT; kt++) {
        cp_wait<1>();
        __syncthreads();                         // stage kt resident
        if (kt + 2 < KT) issue(kt + 2, (kt + 2) % STAGES);
        cp_commit();

        uint32_t sA = sbase + (uint32_t)((kt % STAGES) * SS * 4);
        uint32_t sB = sA + (uint32_t)(SA * 4);
#pragma unroll
        for (int ks = 0; ks < 4; ks++) {
            int kk = ks * 8;
            unsigned af[4][4], bf[8][2];
#pragma unroll
            for (int mi = 0; mi < 4; mi++) {
                uint32_t addr = sA + (uint32_t)(((wm * 64 + mi * 16 + arow) * RS
                                                + kk + acoff) * 4);
                ldsm_x4(af[mi][0], af[mi][1], af[mi][2], af[mi][3], addr);
            }
#pragma unroll
            for (int nj = 0; nj < 4; nj++) {
                uint32_t addr = sB + (uint32_t)(((wn * 64 + nj * 16 + brow) * RS
                                                + kk + bcoff) * 4);
                ldsm_x4(bf[2 * nj][0], bf[2 * nj][1],
                        bf[2 * nj + 1][0], bf[2 * nj + 1][1], addr);
            }
#pragma unroll
            for (int mi = 0; mi < 4; mi++)
#pragma unroll
                for (int ni = 0; ni < 8; ni++)
                    mma_tf32(acc[mi][ni], af[mi], bf[ni]);
        }
        __syncthreads();
    }

    // epilogue (identical rounding chain to rounds 1/6/8)
#pragma unroll
    for (int mi = 0; mi < 4; mi++) {
#pragma unroll
        for (int half = 0; half < 2; half++) {
            int m = m0 + wm * 64 + mi * 16 + group + half * 8;
            if (m >= cnt) continue;
            if (MODE == 0) {
                size_t rowbase = (size_t)(off + m) * NDIM;
#pragma unroll
                for (int ni = 0; ni < 8; ni++) {
                    int c = n0 + wn * 64 + ni * 8 + tig * 2;
                    float v0 = acc[mi][ni][half * 2 + 0] + bias[c];
                    float v1 = acc[mi][ni][half * 2 + 1] + bias[c + 1];
                    g_H[rowbase + c]     = tf32r(v0 / (1.f + __expf(-v0)));
                    g_H[rowbase + c + 1] = tf32r(v1 / (1.f + __expf(-v1)));
                }
            } else {
                int dst = g_dst[e * CAP + m];
                float w = g_wtl[e * CAP + m];
                size_t rowbase = (size_t)dst * NDIM;
#pragma unroll
                for (int ni = 0; ni < 8; ni++) {
                    int c = n0 + wn * 64 + ni * 8 + tig * 2;
                    g_O[rowbase + c]     = (acc[mi][ni][half * 2 + 0] + bias[c]) * w;
                    g_O[rowbase + c + 1] = (acc[mi][ni][half * 2 + 1] + bias[c + 1]) * w;
                }
            }
        }
    }
}

// ---------------- kernel 7: combine the two slots -----------------------------
__global__ void combine_kernel(float4* __restrict__ out) {
    int i = blockIdx.x * 256 + threadIdx.x;
    int t = i >> 8;
    int d4 = i & 255;
    const float4* O4 = (const float4*)g_O;        // device-side symbol
    float4 a = O4[(size_t)(2 * t) * 256 + d4];
    float4 b = O4[(size_t)(2 * t + 1) * 256 + d4];
    out[i] = make_float4(a.x + b.x, a.y + b.y, a.z + b.z, a.w + b.w);
}

// ---------------- launch ------------------------------------------------------
extern "C" void kernel_launch(void* const* d_in, const int* in_sizes, int n_in,
                              void* d_out, int out_size) {
    const float* x  = (const float*)d_in[0];
    const float* gw = (const float*)d_in[1];
    const float* W1 = (const float*)d_in[2];
    const float* b1 = (const float*)d_in[3];
    const float* W2 = (const float*)d_in[4];
    const float* b2 = (const float*)d_in[5];
    float* out = (float*)d_out;

    // opt into >48KB dynamic smem (attribute call, not an allocation)
    constexpr int GEMM_SMEM = 3 * (128 * 36 + 256 * 36) * 4;   // 165,888 B
    cudaFuncSetAttribute(ffn_gemm<DIM, DFF, 0>,
                         cudaFuncAttributeMaxDynamicSharedMemorySize, GEMM_SMEM);
    cudaFuncSetAttribute(ffn_gemm<DFF, DIM, 1>,
                         cudaFuncAttributeMaxDynamicSharedMemorySize, GEMM_SMEM);

    zero_kernel<<<1, 32>>>();
    route_kernel<<<NTOK / 8, 256>>>(x, gw);
    prefix_kernel<<<1, 32>>>();

    // weight prep: tf32 round + transpose to [N][K]
    wprep_kernel<0><<<dim3(DFF / 32, DIM / 32, NEXP), dim3(32, 8)>>>(W1);
    wprep_kernel<1><<<dim3(DIM / 32, DFF / 32, NEXP), dim3(32, 8)>>>(W2);
    gather_kernel<<<dim3(CAP, NEXP), 256>>>(x);

    // GEMM1: (CAP/128) * (DFF/256) = 128 * 16 blocks, z = experts
    ffn_gemm<DIM, DFF, 0><<<dim3((CAP / 128) * (DFF / 256), 1, NEXP), 256, GEMM_SMEM>>>(b1);
    // GEMM2: 128 * (DIM/256 = 4)
    ffn_gemm<DFF, DIM, 1><<<dim3((CAP / 128) * (DIM / 256), 1, NEXP), 256, GEMM_SMEM>>>(b2);

    combine_kernel<<<(NTOK * (DIM / 4)) / 256, 256>>>((float4*)out);
}

// round 12
// speedup vs baseline: 1.6946x; 1.6946x over previous
#include <cuda_runtime.h>
#include <cuda_fp16.h>
#include <cstdint>
#include <cstddef>

// Problem constants
#define NEXP 8
#define TOPK 2
#define DIM 1024
#define DFF 4096
#define NTOK 16384          // B*S
#define CAP  16384          // per-expert capacity
#define RTOT (NTOK * TOPK)  // 32768 expert-rows
#define PADR 128            // row padding for tile overrun

// ---------------- scratch (device globals; DEVICE-CODE REFERENCES ONLY) ------
// RULE (rounds 2-5): never pass these symbols as host-side kernel args — the
// host shadow is ATS-readable on GB300 and silently reads zeros.
__device__ int    g_cnt[NEXP];
__device__ int    g_off[NEXP];
__device__ int    g_tok[NEXP * CAP];
__device__ int    g_dst[NEXP * CAP];
__device__ float  g_wtl[NEXP * CAP];
__device__ __half g_Xh[(size_t)(RTOT + PADR) * DIM];   // gathered x, fp16
__device__ __half g_Hh[(size_t)(RTOT + PADR) * DFF];   // hidden scratch, fp16
__device__ float  g_O [(size_t)RTOT * DIM];            // per-slot outputs, fp32
__device__ __half g_W1h[(size_t)NEXP * DIM * DFF];     // W1^T: [DFF][DIM], fp16
__device__ __half g_W2h[(size_t)NEXP * DFF * DIM];     // W2^T: [DIM][DFF], fp16

// ---------------- helpers ----------------------------------------------------
__device__ __forceinline__ void mma_f16(float c[4], const unsigned a[4], const unsigned b[2]) {
    asm volatile(
        "mma.sync.aligned.m16n8k16.row.col.f32.f16.f16.f32 "
        "{%0,%1,%2,%3}, {%4,%5,%6,%7}, {%8,%9}, {%0,%1,%2,%3};\n"
        : "+f"(c[0]), "+f"(c[1]), "+f"(c[2]), "+f"(c[3])
        : "r"(a[0]), "r"(a[1]), "r"(a[2]), "r"(a[3]), "r"(b[0]), "r"(b[1]));
}
__device__ __forceinline__ void ldsm_x4(unsigned& r0, unsigned& r1, unsigned& r2,
                                        unsigned& r3, uint32_t addr) {
    asm volatile("ldmatrix.sync.aligned.m8n8.x4.shared.b16 {%0,%1,%2,%3}, [%4];"
                 : "=r"(r0), "=r"(r1), "=r"(r2), "=r"(r3) : "r"(addr));
}
__device__ __forceinline__ void cpasync16(uint32_t d, const void* s) {
    asm volatile("cp.async.cg.shared.global [%0], [%1], 16;" :: "r"(d), "l"(s));
}
__device__ __forceinline__ void cp_commit() { asm volatile("cp.async.commit_group;"); }
template <int N>
__device__ __forceinline__ void cp_wait() {
    asm volatile("cp.async.wait_group %0;" :: "n"(N));
}

// ---------------- kernel 0-2: routing ----------------------------------------
__global__ void zero_kernel() {
    if (threadIdx.x < NEXP) g_cnt[threadIdx.x] = 0;
}

__global__ void route_kernel(const float* __restrict__ x, const float* __restrict__ gw) {
    __shared__ float s_gw[NEXP * DIM];
    int tid = threadIdx.x;
    for (int i = tid; i < NEXP * DIM; i += blockDim.x) s_gw[i] = gw[i];
    __syncthreads();

    int warp = tid >> 5, lane = tid & 31;
    int t = blockIdx.x * (blockDim.x >> 5) + warp;
    if (t >= NTOK) return;

    const float* xr = x + (size_t)t * DIM;
    float xv[32];
#pragma unroll
    for (int i = 0; i < 32; i++) xv[i] = xr[i * 32 + lane];

    float logit[NEXP];
#pragma unroll
    for (int e = 0; e < NEXP; e++) {
        float acc = 0.f;
#pragma unroll
        for (int i = 0; i < 32; i++) acc += xv[i] * s_gw[e * DIM + i * 32 + lane];
#pragma unroll
        for (int o = 16; o; o >>= 1) acc += __shfl_xor_sync(0xffffffffu, acc, o);
        logit[e] = acc;
    }

    if (lane == 0) {
        int i0 = 0;
#pragma unroll
        for (int e = 1; e < NEXP; e++) if (logit[e] > logit[i0]) i0 = e;
        int i1 = (i0 == 0) ? 1 : 0;
#pragma unroll
        for (int e = 0; e < NEXP; e++) {
            if (e == i0 || e == i1) continue;
            if (logit[e] > logit[i1]) i1 = e;
        }
        float ee = __expf(logit[i1] - logit[i0]);
        float inv = 1.f / (1.f + ee);
        int p0 = atomicAdd(&g_cnt[i0], 1);
        g_tok[i0 * CAP + p0] = t;  g_dst[i0 * CAP + p0] = t * 2;      g_wtl[i0 * CAP + p0] = inv;
        int p1 = atomicAdd(&g_cnt[i1], 1);
        g_tok[i1 * CAP + p1] = t;  g_dst[i1 * CAP + p1] = t * 2 + 1;  g_wtl[i1 * CAP + p1] = ee * inv;
    }
}

__global__ void prefix_kernel() {
    if (threadIdx.x == 0) {
        int s = 0;
#pragma unroll
        for (int e = 0; e < NEXP; e++) { g_off[e] = s; s += g_cnt[e]; }
    }
}

// ---------------- kernel 3: weight prep: fp16 convert + transpose to [N][K] ---
template <int WHICH>   // 0: W1 (K=DIM, N=DFF) -> g_W1h;  1: W2 (K=DFF, N=DIM) -> g_W2h
__global__ void wprep_kernel(const float* __restrict__ src) {
    constexpr int K = WHICH ? DFF : DIM;
    constexpr int N = WHICH ? DIM : DFF;
    __shared__ float t[32][33];
    __half* dall = WHICH ? g_W2h : g_W1h;          // device-side symbol
    int e = blockIdx.z;
    const float* s = src + (size_t)e * K * N;
    __half* d = dall + (size_t)e * K * N;
    int nb = blockIdx.x * 32, kb = blockIdx.y * 32;
    int tx = threadIdx.x, ty = threadIdx.y;        // block (32, 8)
#pragma unroll
    for (int j = 0; j < 4; j++)
        t[ty + j * 8][tx] = s[(size_t)(kb + ty + j * 8) * N + nb + tx];
    __syncthreads();
#pragma unroll
    for (int j = 0; j < 4; j++)
        d[(size_t)(nb + ty + j * 8) * K + kb + tx] = __float2half_rn(t[tx][ty + j * 8]);
}

// ---------------- kernel 4: gather x -> fp16 ----------------------------------
__global__ void gather_kernel(const float* __restrict__ x) {
    int e = blockIdx.y, m = blockIdx.x;
    if (m >= g_cnt[e]) return;
    int tok = g_tok[e * CAP + m];
    int row = g_off[e] + m;
    const float4* src = (const float4*)(x + (size_t)tok * DIM);
    int t = threadIdx.x;                           // 128 threads, 8 halves each
    float4 a = src[2 * t], b = src[2 * t + 1];
    union { uint4 u; __half2 h[4]; } pk;
    pk.h[0] = __floats2half2_rn(a.x, a.y);
    pk.h[1] = __floats2half2_rn(a.z, a.w);
    pk.h[2] = __floats2half2_rn(b.x, b.y);
    pk.h[3] = __floats2half2_rn(b.z, b.w);
    *(uint4*)(g_Xh + (size_t)row * DIM + t * 8) = pk.u;
}

// ---------------- kernels 5/6: cp.async + ldmatrix fp16 grouped GEMM ----------
// A [m][k] and B = W^T [n][k], fp16 K-major rows, RS=BK+8 halves (row bank
// shift 4 -> LDSM conflict-free). mma m16n8k16 fp32 accumulate.
// MODE 0: Hh = fp16(silu(Xh @ W1 + b1))   (KDIM=DIM,  NDIM=DFF)
// MODE 1: O  = (Hh @ W2 + b2) * wt        (KDIM=DFF,  NDIM=DIM)
template <int KDIM, int NDIM, int MODE>
__global__ void __launch_bounds__(256, 1) ffn_gemm(const float* __restrict__ ball) {
    constexpr int BM = 128, BN = 256, BK = 64, STAGES = 3;
    constexpr int RS = BK + 8;                  // halves: 72 (144B rows)
    constexpr int SAH = BM * RS;                // 9216 halves
    constexpr int SBH = BN * RS;                // 18432 halves
    constexpr int SSH = SAH + SBH;              // 27648 halves = 55296 B / stage
    constexpr int KT = KDIM / BK;
    constexpr int NN = NDIM / BN;
    constexpr int GM = 16;                      // raster group (L2 reuse)

    extern __shared__ __half sm[];

    const __half* Ain = (MODE == 0) ? g_Xh : g_Hh;     // device symbols
    const __half* Wt  = (MODE == 0) ? g_W1h : g_W2h;

    int e = blockIdx.z;
    int cnt = g_cnt[e];
    int per = GM * NN;
    int grp = blockIdx.x / per;
    int rem = blockIdx.x - grp * per;
    int mb = grp * GM + (rem % GM);
    int nb = rem / GM;
    int m0 = mb * BM;
    if (m0 >= cnt) return;
    int n0 = nb * BN;
    int off = g_off[e];

    const __half* Abase = Ain + (size_t)(off + m0) * KDIM;
    const __half* Bbase = Wt + (size_t)e * KDIM * NDIM + (size_t)n0 * KDIM;
    const float* bias = ball + (size_t)e * NDIM;

    int tid = threadIdx.x;
    int warp = tid >> 5, lane = tid & 31;
    int wm = warp & 1, wn = warp >> 1;           // 2 (M) x 4 (N); warp tile 64x64
    int group = lane >> 2, tig = lane & 3;

    uint32_t sbase = (uint32_t)__cvta_generic_to_shared(sm);

    // staging maps (16B = 8-half chunks): A 1024 chunks, B 2048 chunks
    const __half* a_src[4];
    uint32_t a_dst[4];
#pragma unroll
    for (int i = 0; i < 4; i++) {
        int c = tid + 256 * i;                   // 128 rows x 8 chunks
        int r = c >> 3, s = c & 7;
        a_src[i] = Abase + (size_t)r * KDIM + s * 8;
        a_dst[i] = (uint32_t)((r * RS + s * 8) * 2);
    }
    const __half* b_src[8];
    uint32_t b_dst[8];
#pragma unroll
    for (int i = 0; i < 8; i++) {
        int c = tid + 256 * i;                   // 256 rows x 8 chunks
        int n = c >> 3, s = c & 7;
        b_src[i] = Bbase + (size_t)n * KDIM + s * 8;
        b_dst[i] = (uint32_t)((SAH + n * RS + s * 8) * 2);
    }

    auto issue = [&](int kt, int stage) {
        uint32_t sb = sbase + (uint32_t)(stage * SSH * 2);
#pragma unroll
        for (int i = 0; i < 4; i++)
            cpasync16(sb + a_dst[i], a_src[i] + (size_t)kt * BK);
#pragma unroll
        for (int i = 0; i < 8; i++)
            cpasync16(sb + b_dst[i], b_src[i] + (size_t)kt * BK);
    };

    // ldmatrix per-thread components (textbook fp16 recipe)
    int lrow = lane & 15;                        // row within 16-block
    int lchk = (lane >> 4) * 8;                  // k offset in halves: 0 / 8

    float acc[4][8][4];
#pragma unroll
    for (int mi = 0; mi < 4; mi++)
#pragma unroll
        for (int ni = 0; ni < 8; ni++)
#pragma unroll
            for (int r = 0; r < 4; r++) acc[mi][ni][r] = 0.f;

    issue(0, 0); cp_commit();
    issue(1, 1); cp_commit();

    for (int kt = 0; kt < KT; kt++) {
        cp_wait<1>();
        __syncthreads();                         // stage kt resident
        if (kt + 2 < KT) issue(kt + 2, (kt + 2) % STAGES);
        cp_commit();

        uint32_t sA = sbase + (uint32_t)((kt % STAGES) * SSH * 2);
        uint32_t sB = sA + (uint32_t)(SAH * 2);
#pragma unroll
        for (int ks = 0; ks < 4; ks++) {         // K=16 per step
            int kk = ks * 16;
            unsigned af[4][4], bf[8][2];
#pragma unroll
            for (int mi = 0; mi < 4; mi++) {
                uint32_t addr = sA + (uint32_t)(((wm * 64 + mi * 16 + lrow) * RS
                                                + kk + lchk) * 2);
                // A x4 -> {a0,a1,a2,a3} directly
                ldsm_x4(af[mi][0], af[mi][1], af[mi][2], af[mi][3], addr);
            }
#pragma unroll
            for (int nj = 0; nj < 4; nj++) {
                uint32_t addr = sB + (uint32_t)(((wn * 64 + nj * 16 + lrow) * RS
                                                + kk + lchk) * 2);
                unsigned r0, r1, r2, r3;
                ldsm_x4(r0, r1, r2, r3, addr);
                bf[2 * nj][0]     = r0;  bf[2 * nj][1]     = r2;   // n 0-7:  k0-7,k8-15
                bf[2 * nj + 1][0] = r1;  bf[2 * nj + 1][1] = r3;   // n 8-15
            }
#pragma unroll
            for (int mi = 0; mi < 4; mi++)
#pragma unroll
                for (int ni = 0; ni < 8; ni++)
                    mma_f16(acc[mi][ni], af[mi], bf[ni]);
        }
        __syncthreads();
    }

    // epilogue (same acc layout as proven rounds; fp32 math, fp16/fp32 stores)
#pragma unroll
    for (int mi = 0; mi < 4; mi++) {
#pragma unroll
        for (int half = 0; half < 2; half++) {
            int m = m0 + wm * 64 + mi * 16 + group + half * 8;
            if (m >= cnt) continue;
            if (MODE == 0) {
                size_t rowbase = (size_t)(off + m) * NDIM;
#pragma unroll
                for (int ni = 0; ni < 8; ni++) {
                    int c = n0 + wn * 64 + ni * 8 + tig * 2;
                    float v0 = acc[mi][ni][half * 2 + 0] + bias[c];
                    float v1 = acc[mi][ni][half * 2 + 1] + bias[c + 1];
                    v0 = v0 / (1.f + __expf(-v0));
                    v1 = v1 / (1.f + __expf(-v1));
                    *(__half2*)(g_Hh + rowbase + c) = __floats2half2_rn(v0, v1);
                }
            } else {
                int dst = g_dst[e * CAP + m];
                float w = g_wtl[e * CAP + m];
                size_t rowbase = (size_t)dst * NDIM;
#pragma unroll
                for (int ni = 0; ni < 8; ni++) {
                    int c = n0 + wn * 64 + ni * 8 + tig * 2;
                    float2 v;
                    v.x = (acc[mi][ni][half * 2 + 0] + bias[c]) * w;
                    v.y = (acc[mi][ni][half * 2 + 1] + bias[c + 1]) * w;
                    *(float2*)(g_O + rowbase + c) = v;
                }
            }
        }
    }
}

// ---------------- kernel 7: combine the two slots -----------------------------
__global__ void combine_kernel(float4* __restrict__ out) {
    int i = blockIdx.x * 256 + threadIdx.x;
    int t = i >> 8;
    int d4 = i & 255;
    const float4* O4 = (const float4*)g_O;        // device-side symbol
    float4 a = O4[(size_t)(2 * t) * 256 + d4];
    float4 b = O4[(size_t)(2 * t + 1) * 256 + d4];
    out[i] = make_float4(a.x + b.x, a.y + b.y, a.z + b.z, a.w + b.w);
}

// ---------------- launch ------------------------------------------------------
extern "C" void kernel_launch(void* const* d_in, const int* in_sizes, int n_in,
                              void* d_out, int out_size) {
    const float* x  = (const float*)d_in[0];
    const float* gw = (const float*)d_in[1];
    const float* W1 = (const float*)d_in[2];
    const float* b1 = (const float*)d_in[3];
    const float* W2 = (const float*)d_in[4];
    const float* b2 = (const float*)d_in[5];
    float* out = (float*)d_out;

    // opt into >48KB dynamic smem (attribute call, not an allocation)
    constexpr int GEMM_SMEM = 3 * (128 * 72 + 256 * 72) * 2;   // 165,888 B
    cudaFuncSetAttribute(ffn_gemm<DIM, DFF, 0>,
                         cudaFuncAttributeMaxDynamicSharedMemorySize, GEMM_SMEM);
    cudaFuncSetAttribute(ffn_gemm<DFF, DIM, 1>,
                         cudaFuncAttributeMaxDynamicSharedMemorySize, GEMM_SMEM);

    zero_kernel<<<1, 32>>>();
    route_kernel<<<NTOK / 8, 256>>>(x, gw);
    prefix_kernel<<<1, 32>>>();

    // weight prep: fp16 convert + transpose to [N][K]
    wprep_kernel<0><<<dim3(DFF / 32, DIM / 32, NEXP), dim3(32, 8)>>>(W1);
    wprep_kernel<1><<<dim3(DIM / 32, DFF / 32, NEXP), dim3(32, 8)>>>(W2);
    gather_kernel<<<dim3(CAP, NEXP), 128>>>(x);

    // GEMM1: (CAP/128) * (DFF/256) = 128 * 16 blocks, z = experts
    ffn_gemm<DIM, DFF, 0><<<dim3((CAP / 128) * (DFF / 256), 1, NEXP), 256, GEMM_SMEM>>>(b1);
    // GEMM2: 128 * (DIM/256 = 4)
    ffn_gemm<DFF, DIM, 1><<<dim3((CAP / 128) * (DIM / 256), 1, NEXP), 256, GEMM_SMEM>>>(b2);

    combine_kernel<<<(NTOK * (DIM / 4)) / 256, 256>>>((float4*)out);
}